// round 1
// baseline (speedup 1.0000x reference)
#include <cuda_runtime.h>
#include <cuda_bf16.h>
#include <cstdint>

// Problem constants
#define BB 32
#define SV 4096
#define SQ 1152
#define DD 128
#define FD 96
#define CH 16               // s-chunks in v pass
#define ROWS (SV / CH)      // 256 rows per chunk
#define NPOOL (SQ / 12 * DD) // 12288 pooled chunks per batch (k*96+f)

// Scratch (no allocations allowed)
__device__ float g_part[CH * BB * 6 * DD];   // per-chunk partial power sums
__device__ float g_qpool[BB * NPOOL];        // 12-element sums of q
__device__ float g_att0[BB * DD];
__device__ float g_pI[BB * FD];
__device__ float g_L[BB], g_sa[BB], g_sa2[BB];
__device__ float g_scale[FD], g_shift[FD];

// ---------------------------------------------------------------------------
// K1: streaming power sums S1..S6 over v (column sums per (b,d))
// grid (CH, B), block 256 = 8 warps; lane owns 4 d-columns (float4)
// ---------------------------------------------------------------------------
__global__ void k_vpow(const float* __restrict__ v) {
    int chunk = blockIdx.x, b = blockIdx.y;
    int t = threadIdx.x, lane = t & 31, w = t >> 5;
    const float4* vp = (const float4*)(v + ((size_t)b * SV + (size_t)chunk * ROWS) * DD);

    float s1[4] = {0,0,0,0}, s2[4] = {0,0,0,0}, s3[4] = {0,0,0,0};
    float s4[4] = {0,0,0,0}, s5[4] = {0,0,0,0}, s6[4] = {0,0,0,0};

    #pragma unroll 4
    for (int i = 0; i < ROWS / 8; i++) {
        int r = w + 8 * i;
        float4 x = vp[r * 32 + lane];
        float xv[4] = {x.x, x.y, x.z, x.w};
        #pragma unroll
        for (int j = 0; j < 4; j++) {
            float a = xv[j];
            float a2 = a * a;
            float a3 = a2 * a;
            s1[j] += a;
            s2[j] += a2;
            s3[j] += a3;
            s4[j] = fmaf(a2, a2, s4[j]);
            s5[j] = fmaf(a3, a2, s5[j]);
            s6[j] = fmaf(a3, a3, s6[j]);
        }
    }

    __shared__ float sh[8][6][DD];
    int d0 = lane * 4;
    #pragma unroll
    for (int j = 0; j < 4; j++) {
        sh[w][0][d0 + j] = s1[j];
        sh[w][1][d0 + j] = s2[j];
        sh[w][2][d0 + j] = s3[j];
        sh[w][3][d0 + j] = s4[j];
        sh[w][4][d0 + j] = s5[j];
        sh[w][5][d0 + j] = s6[j];
    }
    __syncthreads();
    for (int idx = t; idx < 6 * DD; idx += 256) {
        int k = idx >> 7, d = idx & 127;
        float acc = 0.f;
        #pragma unroll
        for (int ww = 0; ww < 8; ww++) acc += sh[ww][k][d];
        g_part[((chunk * BB + b) * 6 + k) * DD + d] = acc;
    }
}

// ---------------------------------------------------------------------------
// K2: 12-element pooled sums of q (flat memory chunks)
// ---------------------------------------------------------------------------
__global__ void k_qpool(const float* __restrict__ q) {
    int i = blockIdx.x * blockDim.x + threadIdx.x;   // 0 .. B*NPOOL-1
    if (i >= BB * NPOOL) return;
    const float4* p = (const float4*)q + (size_t)i * 3;
    float4 a = p[0], bq = p[1], c = p[2];
    g_qpool[i] = ((a.x + a.y) + (a.z + a.w))
               + ((bq.x + bq.y) + (bq.z + bq.w))
               + ((c.x + c.y) + (c.z + c.w));
}

// ---------------------------------------------------------------------------
// K3: per-batch solve. grid B, block 256.
// ---------------------------------------------------------------------------
__global__ void k_solve(const float* __restrict__ v,
                        const float* __restrict__ hmat,
                        const float* __restrict__ hbias) {
    int b = blockIdx.x;
    int t = threadIdx.x;

    __shared__ float sS[6][DD];
    __shared__ float sqs[DD];
    __shared__ float shm[3], shb[3];
    __shared__ float sred[8];
    __shared__ float sred5[8][5];
    __shared__ float s_sumq;

    // a) combine per-chunk partial power sums
    for (int idx = t; idx < 6 * DD; idx += 256) {
        int k = idx >> 7, d = idx & 127;
        float acc = 0.f;
        #pragma unroll 4
        for (int c = 0; c < CH; c++)
            acc += g_part[((c * BB + b) * 6 + k) * DD + d];
        sS[k][d] = acc;
    }

    // b) qs[d] = sum over f of qpool row; also feeds sumq
    float myqs = 0.f;
    if (t < DD) {
        const float* qp = g_qpool + (size_t)b * NPOOL + t * FD;
        #pragma unroll 4
        for (int f = 0; f < FD; f++) myqs += qp[f];
        sqs[t] = myqs;
    }

    // c) hm[c], hbias[c]
    if (t < 3) {
        float a = 0.f;
        for (int x = 0; x < FD; x++) a += hmat[t * FD + x];
        shm[t] = a;
        shb[t] = hbias[t];
    }
    __syncthreads();

    // sumq = sum of sqs
    {
        float val = (t < DD) ? myqs : 0.f;
        #pragma unroll
        for (int o = 16; o; o >>= 1) val += __shfl_down_sync(0xffffffffu, val, o);
        if ((t & 31) == 0) sred[t >> 5] = val;
        __syncthreads();
        if (t == 0) {
            float s = 0.f;
            #pragma unroll
            for (int i = 0; i < 8; i++) s += sred[i];
            s_sumq = s;
        }
        __syncthreads();
    }
    float sumq = s_sumq;

    // d) per-d: alpha per channel, Z via Taylor (|alpha*v| < ~0.1), softmax rows 0..2
    float e0 = 0.f, e1 = 0.f, e2 = 0.f, S1v = 0.f, r2 = 0.f, r3 = 0.f;
    if (t < DD) {
        int d = t;
        float S1 = sS[0][d], S2 = sS[1][d], S3 = sS[2][d];
        float S4 = sS[3][d], S5 = sS[4][d], S6 = sS[5][d];
        S1v = S1;
        const float* vb = v + (size_t)b * SV * DD + d;
        float v0 = vb[0], v1 = vb[DD], v2 = vb[2 * DD];
        #pragma unroll
        for (int c = 0; c < 3; c++) {
            float A  = shm[c] * sumq;
            float Bc = shb[c];
            float n2 = A * A * S2 + 2.f * A * Bc * S1 + (float)SV * Bc * Bc;
            float al = A * rsqrtf(n2);
            float Z = (float)SV
                + al * (S1 + al * (0.5f * S2 + al * ((1.f/6.f) * S3
                + al * ((1.f/24.f) * S4 + al * ((1.f/120.f) * S5
                + al * (1.f/720.f) * S6)))));
            float iZ = 1.f / Z;
            e0 += __expf(al * v0) * iZ;
            e1 += __expf(al * v1) * iZ;
            e2 += __expf(al * v2) * iZ;
        }
        g_att0[b * DD + t] = e0;
        r2 = e1 * sqs[t];
        r3 = e2 * sqs[t];
    }

    // e) reductions: sa, sa2, dot1, dot2, vsum
    {
        float r[5] = {e0, e0 * e0, r2, r3, S1v};
        #pragma unroll
        for (int o = 16; o; o >>= 1) {
            #pragma unroll
            for (int j = 0; j < 5; j++) r[j] += __shfl_down_sync(0xffffffffu, r[j], o);
        }
        if ((t & 31) == 0) {
            #pragma unroll
            for (int j = 0; j < 5; j++) sred5[t >> 5][j] = r[j];
        }
        __syncthreads();
        if (t == 0) {
            float sa = 0.f, sa2 = 0.f, dot1 = 0.f, dot2 = 0.f, vs = 0.f;
            #pragma unroll
            for (int i = 0; i < 8; i++) {
                sa += sred5[i][0]; sa2 += sred5[i][1];
                dot1 += sred5[i][2]; dot2 += sred5[i][3];
                vs += sred5[i][4];
            }
            g_sa[b] = sa;
            g_sa2[b] = sa2;
            g_L[b] = vs * dot1 + vs * dot2;
        }
    }

    // f) pooledInner[b,f] = (1/12) * sum_k S1[k] * qpool[b,k,f]
    if (t < FD) {
        float acc = 0.f;
        const float* qp = g_qpool + (size_t)b * NPOOL + t;
        #pragma unroll 4
        for (int k = 0; k < DD; k++) acc += sS[0][k] * qp[k * FD];
        g_pI[b * FD + t] = acc * (1.f / 12.f);
    }
}

// ---------------------------------------------------------------------------
// K4: batchnorm stats (logits never materialized). 1 block.
// ---------------------------------------------------------------------------
__global__ void k_stats(const float* __restrict__ gamma,
                        const float* __restrict__ beta) {
    int f = threadIdx.x;
    if (f >= FD) return;
    float m = 0.f, m2 = 0.f;
    for (int b = 0; b < BB; b++) {
        float pi = g_pI[b * FD + f];
        float L  = g_L[b];
        float sa = g_sa[b];
        float sa2 = g_sa2[b];
        m  += pi * sa + (float)DD * L;
        m2 += pi * pi * sa2 + 2.f * pi * L * sa + (float)DD * L * L;
    }
    const float inv = 1.f / (float)(BB * DD);
    float mean = m * inv;
    float var  = m2 * inv - mean * mean;
    float scale = gamma[f] * rsqrtf(var + 1e-5f);
    g_scale[f] = scale;
    g_shift[f] = beta[f] - mean * scale;
}

// ---------------------------------------------------------------------------
// K5: write output [B, FD, D]
// ---------------------------------------------------------------------------
__global__ void k_out(float* __restrict__ out) {
    int f = blockIdx.x, b = blockIdx.y, d = threadIdx.x;
    float val = g_att0[b * DD + d] * g_pI[b * FD + f] + g_L[b];
    out[((size_t)b * FD + f) * DD + d] = val * g_scale[f] + g_shift[f];
}

extern "C" void kernel_launch(void* const* d_in, const int* in_sizes, int n_in,
                              void* d_out, int out_size) {
    const float* q     = (const float*)d_in[0];
    const float* v     = (const float*)d_in[1];
    const float* hmat  = (const float*)d_in[2];
    const float* hbias = (const float*)d_in[3];
    const float* gamma = (const float*)d_in[4];
    const float* beta  = (const float*)d_in[5];
    float* out = (float*)d_out;

    k_vpow<<<dim3(CH, BB), 256>>>(v);
    k_qpool<<<(BB * NPOOL) / 256, 256>>>(q);
    k_solve<<<BB, 256>>>(v, hmat, hbias);
    k_stats<<<1, 128>>>(gamma, beta);
    k_out<<<dim3(FD, BB), DD>>>(out);
}

// round 2
// speedup vs baseline: 1.0372x; 1.0372x over previous
#include <cuda_runtime.h>
#include <cuda_bf16.h>
#include <cstdint>

// Problem constants
#define BB 32
#define SV 4096
#define SQ 1152
#define DD 128
#define FD 96
#define CH 16                 // s-chunks in v pass
#define ROWS (SV / CH)        // 256 rows per chunk
#define NPOOL (SQ / 12 * DD)  // 12288 pooled 12-chunks per batch
#define VBLOCKS (CH * BB)     // 512
#define QBLOCKS ((BB * NPOOL) / 256)  // 1536

// Scratch (no allocations allowed)
__device__ float g_part[CH * BB * 6 * DD];   // per-chunk partial power sums
__device__ float g_qpool[BB * NPOOL];        // 12-element sums of q
__device__ float g_att0[BB * DD];
__device__ float g_pI[BB * FD];
__device__ float g_L[BB], g_sa[BB], g_sa2[BB];

// ---------------------------------------------------------------------------
// K1 (fused): blocks [0, VBLOCKS) -> streaming power sums S1..S6 over v
//             blocks [VBLOCKS, VBLOCKS+QBLOCKS) -> 12-element pooled sums of q
// 256 threads per block.
// ---------------------------------------------------------------------------
__global__ void k_pass1(const float* __restrict__ v, const float* __restrict__ q) {
    int t = threadIdx.x;

    if (blockIdx.x >= VBLOCKS) {
        // ---- q pooled sums ----
        int i = (blockIdx.x - VBLOCKS) * 256 + t;      // 0 .. B*NPOOL-1
        const float4* p = (const float4*)q + (size_t)i * 3;
        float4 a = p[0], bq = p[1], c = p[2];
        g_qpool[i] = ((a.x + a.y) + (a.z + a.w))
                   + ((bq.x + bq.y) + (bq.z + bq.w))
                   + ((c.x + c.y) + (c.z + c.w));
        return;
    }

    // ---- v power sums ----
    int chunk = blockIdx.x & (CH - 1);
    int b = blockIdx.x / CH;
    int lane = t & 31, w = t >> 5;
    const float4* vp = (const float4*)(v + ((size_t)b * SV + (size_t)chunk * ROWS) * DD);

    float s1[4] = {0,0,0,0}, s2[4] = {0,0,0,0}, s3[4] = {0,0,0,0};
    float s4[4] = {0,0,0,0}, s5[4] = {0,0,0,0}, s6[4] = {0,0,0,0};

    #pragma unroll 4
    for (int i = 0; i < ROWS / 8; i++) {
        int r = w + 8 * i;
        float4 x = vp[r * 32 + lane];
        float xv[4] = {x.x, x.y, x.z, x.w};
        #pragma unroll
        for (int j = 0; j < 4; j++) {
            float a = xv[j];
            float a2 = a * a;
            float a3 = a2 * a;
            s1[j] += a;
            s2[j] += a2;
            s3[j] += a3;
            s4[j] = fmaf(a2, a2, s4[j]);
            s5[j] = fmaf(a3, a2, s5[j]);
            s6[j] = fmaf(a3, a3, s6[j]);
        }
    }

    __shared__ float sh[8][6][DD];
    int d0 = lane * 4;
    #pragma unroll
    for (int j = 0; j < 4; j++) {
        sh[w][0][d0 + j] = s1[j];
        sh[w][1][d0 + j] = s2[j];
        sh[w][2][d0 + j] = s3[j];
        sh[w][3][d0 + j] = s4[j];
        sh[w][4][d0 + j] = s5[j];
        sh[w][5][d0 + j] = s6[j];
    }
    __syncthreads();
    for (int idx = t; idx < 6 * DD; idx += 256) {
        int k = idx >> 7, d = idx & 127;
        float acc = 0.f;
        #pragma unroll
        for (int ww = 0; ww < 8; ww++) acc += sh[ww][k][d];
        g_part[((chunk * BB + b) * 6 + k) * DD + d] = acc;
    }
}

// ---------------------------------------------------------------------------
// K2: per-batch solve. grid B, block 256.
// ---------------------------------------------------------------------------
__global__ void k_solve(const float* __restrict__ v,
                        const float* __restrict__ hmat,
                        const float* __restrict__ hbias) {
    int b = blockIdx.x;
    int t = threadIdx.x;

    __shared__ float sS[6][DD];
    __shared__ float sqs[DD];
    __shared__ float shm[3], shb[3];
    __shared__ float sred[8];
    __shared__ float sred5[8][5];
    __shared__ float s_sumq;

    // a) combine per-chunk partial power sums
    for (int idx = t; idx < 6 * DD; idx += 256) {
        int k = idx >> 7, d = idx & 127;
        float acc = 0.f;
        #pragma unroll
        for (int c = 0; c < CH; c++)
            acc += g_part[((c * BB + b) * 6 + k) * DD + d];
        sS[k][d] = acc;
    }

    // b) qs[d] = sum over f of qpool row
    float myqs = 0.f;
    if (t < DD) {
        const float* qp = g_qpool + (size_t)b * NPOOL + t * FD;
        #pragma unroll 4
        for (int f = 0; f < FD; f++) myqs += qp[f];
        sqs[t] = myqs;
    }

    // c) hm[c], hbias[c]
    if (t < 3) {
        float a = 0.f;
        for (int x = 0; x < FD; x++) a += hmat[t * FD + x];
        shm[t] = a;
        shb[t] = hbias[t];
    }
    __syncthreads();

    // sumq
    {
        float val = (t < DD) ? myqs : 0.f;
        #pragma unroll
        for (int o = 16; o; o >>= 1) val += __shfl_down_sync(0xffffffffu, val, o);
        if ((t & 31) == 0) sred[t >> 5] = val;
        __syncthreads();
        if (t == 0) {
            float s = 0.f;
            #pragma unroll
            for (int i = 0; i < 8; i++) s += sred[i];
            s_sumq = s;
        }
        __syncthreads();
    }
    float sumq = s_sumq;

    // d) per-d alpha/Z via Taylor; softmax rows 0..2
    float e0 = 0.f, e1 = 0.f, e2 = 0.f, S1v = 0.f, r2 = 0.f, r3 = 0.f;
    if (t < DD) {
        int d = t;
        float S1 = sS[0][d], S2 = sS[1][d], S3 = sS[2][d];
        float S4 = sS[3][d], S5 = sS[4][d], S6 = sS[5][d];
        S1v = S1;
        const float* vb = v + (size_t)b * SV * DD + d;
        float v0 = vb[0], v1 = vb[DD], v2 = vb[2 * DD];
        #pragma unroll
        for (int c = 0; c < 3; c++) {
            float A  = shm[c] * sumq;
            float Bc = shb[c];
            float n2 = A * A * S2 + 2.f * A * Bc * S1 + (float)SV * Bc * Bc;
            float al = A * rsqrtf(n2);
            float Z = (float)SV
                + al * (S1 + al * (0.5f * S2 + al * ((1.f/6.f) * S3
                + al * ((1.f/24.f) * S4 + al * ((1.f/120.f) * S5
                + al * (1.f/720.f) * S6)))));
            float iZ = 1.f / Z;
            e0 += __expf(al * v0) * iZ;
            e1 += __expf(al * v1) * iZ;
            e2 += __expf(al * v2) * iZ;
        }
        g_att0[b * DD + t] = e0;
        r2 = e1 * sqs[t];
        r3 = e2 * sqs[t];
    }

    // e) reductions: sa, sa2, dot1, dot2, vsum
    {
        float r[5] = {e0, e0 * e0, r2, r3, S1v};
        #pragma unroll
        for (int o = 16; o; o >>= 1) {
            #pragma unroll
            for (int j = 0; j < 5; j++) r[j] += __shfl_down_sync(0xffffffffu, r[j], o);
        }
        if ((t & 31) == 0) {
            #pragma unroll
            for (int j = 0; j < 5; j++) sred5[t >> 5][j] = r[j];
        }
        __syncthreads();
        if (t == 0) {
            float sa = 0.f, sa2 = 0.f, dot1 = 0.f, dot2 = 0.f, vs = 0.f;
            #pragma unroll
            for (int i = 0; i < 8; i++) {
                sa += sred5[i][0]; sa2 += sred5[i][1];
                dot1 += sred5[i][2]; dot2 += sred5[i][3];
                vs += sred5[i][4];
            }
            g_sa[b] = sa;
            g_sa2[b] = sa2;
            g_L[b] = vs * dot1 + vs * dot2;
        }
    }

    // f) pooledInner[b,f]
    if (t < FD) {
        float acc = 0.f;
        const float* qp = g_qpool + (size_t)b * NPOOL + t;
        #pragma unroll 4
        for (int k = 0; k < DD; k++) acc += sS[0][k] * qp[k * FD];
        g_pI[b * FD + t] = acc * (1.f / 12.f);
    }
}

// ---------------------------------------------------------------------------
// K3 (fused BN-stats + output). grid FD, block 128.
// Threads t<32 load per-batch scalars in PARALLEL (was the 13.5us serial bug),
// warp-reduce to mean/var for channel f, then the block writes its f-row.
// ---------------------------------------------------------------------------
__global__ void k_finish(const float* __restrict__ gamma,
                         const float* __restrict__ beta,
                         float* __restrict__ out) {
    int f = blockIdx.x;
    int t = threadIdx.x;

    __shared__ float sPI[BB], sL[BB];
    __shared__ float s_scale, s_shift;

    float m = 0.f, m2 = 0.f;
    if (t < BB) {
        float pi  = g_pI[t * FD + f];
        float L   = g_L[t];
        float sa  = g_sa[t];
        float sa2 = g_sa2[t];
        sPI[t] = pi;
        sL[t]  = L;
        m  = pi * sa + (float)DD * L;
        m2 = pi * pi * sa2 + 2.f * pi * L * sa + (float)DD * L * L;
    }
    if (t < 32) {
        #pragma unroll
        for (int o = 16; o; o >>= 1) {
            m  += __shfl_down_sync(0xffffffffu, m,  o);
            m2 += __shfl_down_sync(0xffffffffu, m2, o);
        }
        if (t == 0) {
            const float inv = 1.f / (float)(BB * DD);
            float mean = m * inv;
            float var  = m2 * inv - mean * mean;
            float scale = gamma[f] * rsqrtf(var + 1e-5f);
            s_scale = scale;
            s_shift = beta[f] - mean * scale;
        }
    }
    __syncthreads();
    float scale = s_scale, shift = s_shift;

    int d = t;
    #pragma unroll 4
    for (int b = 0; b < BB; b++) {
        float val = g_att0[b * DD + d] * sPI[b] + sL[b];
        out[((size_t)b * FD + f) * DD + d] = val * scale + shift;
    }
}

extern "C" void kernel_launch(void* const* d_in, const int* in_sizes, int n_in,
                              void* d_out, int out_size) {
    const float* q     = (const float*)d_in[0];
    const float* v     = (const float*)d_in[1];
    const float* hmat  = (const float*)d_in[2];
    const float* hbias = (const float*)d_in[3];
    const float* gamma = (const float*)d_in[4];
    const float* beta  = (const float*)d_in[5];
    float* out = (float*)d_out;

    k_pass1<<<VBLOCKS + QBLOCKS, 256>>>(v, q);
    k_solve<<<BB, 256>>>(v, hmat, hbias);
    k_finish<<<FD, 128>>>(gamma, beta, out);
}

// round 3
// speedup vs baseline: 1.4079x; 1.3575x over previous
#include <cuda_runtime.h>
#include <cuda_bf16.h>
#include <cstdint>

// Problem constants
#define BB 32
#define SV 4096
#define SQ 1152
#define DD 128
#define FD 96
#define NS 4                  // power sums kept: S1..S4
#define CH 16                 // s-chunks in v pass
#define ROWS (SV / CH)        // 256 rows per chunk
#define NPOOL (SQ / 12 * DD)  // 12288 pooled 12-sums per batch
#define VBLOCKS (CH * BB)     // 512
#define QB_PER_B 16           // q blocks per batch; each owns 8 k-rows
#define QBLOCKS (BB * QB_PER_B)  // 512

// Scratch (no allocations allowed)
__device__ float g_part[CH * BB * NS * DD];  // per-chunk partial power sums
__device__ float g_qpool[BB * NPOOL];        // 12-element pooled sums of q
__device__ float g_qs[BB * DD];              // row sums of qr (sum over Sq)
__device__ float g_att0[BB * DD];
__device__ float g_pI[BB * FD];
__device__ float g_L[BB], g_sa[BB], g_sa2[BB];

// ---------------------------------------------------------------------------
// K1 (fused): blocks [0, VBLOCKS) -> streaming power sums S1..S4 over v
//             blocks [VBLOCKS, ..) -> pooled sums of q + per-row sums g_qs
// 256 threads per block.
// ---------------------------------------------------------------------------
__global__ void k_pass1(const float* __restrict__ v, const float* __restrict__ q) {
    int t = threadIdx.x;

    if (blockIdx.x >= VBLOCKS) {
        // ---- q part: 8 complete k-rows (each row = 1152 floats -> 96 pooled) ----
        int qb = blockIdx.x - VBLOCKS;
        int b  = qb / QB_PER_B;
        int kg = qb % QB_PER_B;           // group of 8 k-rows
        const float4* p = (const float4*)(q + (size_t)b * SQ * DD) + (size_t)kg * 2304;
        __shared__ float sp[768];
        #pragma unroll
        for (int j = 0; j < 3; j++) {
            int pidx = t + j * 256;       // local pooled index 0..767
            const float4* pp = p + pidx * 3;
            float4 a = pp[0], c = pp[1], e = pp[2];
            float s = ((a.x + a.y) + (a.z + a.w))
                    + ((c.x + c.y) + (c.z + c.w))
                    + ((e.x + e.y) + (e.z + e.w));
            sp[pidx] = s;
            g_qpool[(size_t)b * NPOOL + kg * 768 + pidx] = s;
        }
        __syncthreads();
        if (t < 8) {
            float acc = 0.f;
            #pragma unroll
            for (int f = 0; f < 96; f++) acc += sp[t * 96 + f];
            g_qs[b * DD + kg * 8 + t] = acc;
        }
        return;
    }

    // ---- v power sums S1..S4 ----
    int chunk = blockIdx.x & (CH - 1);
    int b = blockIdx.x / CH;
    int lane = t & 31, w = t >> 5;
    const float4* vp = (const float4*)(v + ((size_t)b * SV + (size_t)chunk * ROWS) * DD);

    float s1[4] = {0,0,0,0}, s2[4] = {0,0,0,0}, s3[4] = {0,0,0,0}, s4[4] = {0,0,0,0};

    #pragma unroll 8
    for (int i = 0; i < ROWS / 8; i++) {
        int r = w + 8 * i;
        float4 x = vp[r * 32 + lane];
        float xv[4] = {x.x, x.y, x.z, x.w};
        #pragma unroll
        for (int j = 0; j < 4; j++) {
            float a = xv[j];
            float a2 = a * a;
            s1[j] += a;
            s2[j] += a2;
            s3[j] = fmaf(a2, a, s3[j]);
            s4[j] = fmaf(a2, a2, s4[j]);
        }
    }

    __shared__ float sh[8][NS][DD];
    int d0 = lane * 4;
    #pragma unroll
    for (int j = 0; j < 4; j++) {
        sh[w][0][d0 + j] = s1[j];
        sh[w][1][d0 + j] = s2[j];
        sh[w][2][d0 + j] = s3[j];
        sh[w][3][d0 + j] = s4[j];
    }
    __syncthreads();
    #pragma unroll
    for (int idx = t; idx < NS * DD; idx += 256) {
        int k = idx >> 7, d = idx & 127;
        float acc = 0.f;
        #pragma unroll
        for (int ww = 0; ww < 8; ww++) acc += sh[ww][k][d];
        g_part[((chunk * BB + b) * NS + k) * DD + d] = acc;
    }
}

// ---------------------------------------------------------------------------
// K2: per-batch solve. grid B, block 256.
// ---------------------------------------------------------------------------
__global__ void k_solve(const float* __restrict__ v,
                        const float* __restrict__ hmat,
                        const float* __restrict__ hbias) {
    int b = blockIdx.x;
    int t = threadIdx.x;

    __shared__ float sS[NS][DD];
    __shared__ float sqs[DD];
    __shared__ float shm[3], shb[3];
    __shared__ float sred[8];
    __shared__ float sred5[8][5];
    __shared__ float spf[2][FD];
    __shared__ float s_sumq;

    // a) combine per-chunk partial power sums (all loads independent -> 1 trip)
    #pragma unroll
    for (int idx = t; idx < NS * DD; idx += 256) {
        int k = idx >> 7, d = idx & 127;
        float acc = 0.f;
        #pragma unroll
        for (int c = 0; c < CH; c++)
            acc += g_part[((c * BB + b) * NS + k) * DD + d];
        sS[k][d] = acc;
    }

    // b) qs from g_qs (precomputed in pass1)
    float myqs = 0.f;
    if (t < DD) {
        myqs = g_qs[b * DD + t];
        sqs[t] = myqs;
    }

    // c) hm[c], hbias[c]
    if (t < 3) {
        float a = 0.f;
        for (int x = 0; x < FD; x++) a += hmat[t * FD + x];
        shm[t] = a;
        shb[t] = hbias[t];
    }
    __syncthreads();

    // sumq
    {
        float val = (t < DD) ? myqs : 0.f;
        #pragma unroll
        for (int o = 16; o; o >>= 1) val += __shfl_down_sync(0xffffffffu, val, o);
        if ((t & 31) == 0) sred[t >> 5] = val;
        __syncthreads();
        if (t == 0) {
            float s = 0.f;
            #pragma unroll
            for (int i = 0; i < 8; i++) s += sred[i];
            s_sumq = s;
        }
        __syncthreads();
    }
    float sumq = s_sumq;

    // d) per-d alpha/Z via Taylor (S1..S4); softmax rows 0..2
    float e0 = 0.f, e1 = 0.f, e2 = 0.f, S1v = 0.f, r2 = 0.f, r3 = 0.f;
    if (t < DD) {
        int d = t;
        float S1 = sS[0][d], S2 = sS[1][d], S3 = sS[2][d], S4 = sS[3][d];
        S1v = S1;
        const float* vb = v + (size_t)b * SV * DD + d;
        float v0 = vb[0], v1 = vb[DD], v2 = vb[2 * DD];
        #pragma unroll
        for (int c = 0; c < 3; c++) {
            float A  = shm[c] * sumq;
            float Bc = shb[c];
            float n2 = A * A * S2 + 2.f * A * Bc * S1 + (float)SV * Bc * Bc;
            float al = A * rsqrtf(n2);
            float Z = (float)SV
                + al * (S1 + al * (0.5f * S2 + al * ((1.f/6.f) * S3
                + al * (1.f/24.f) * S4)));
            float iZ = 1.f / Z;
            e0 += __expf(al * v0) * iZ;
            e1 += __expf(al * v1) * iZ;
            e2 += __expf(al * v2) * iZ;
        }
        g_att0[b * DD + t] = e0;
        r2 = e1 * sqs[t];
        r3 = e2 * sqs[t];
    }

    // e) reductions: sa, sa2, dot1, dot2, vsum
    {
        float r[5] = {e0, e0 * e0, r2, r3, S1v};
        #pragma unroll
        for (int o = 16; o; o >>= 1) {
            #pragma unroll
            for (int j = 0; j < 5; j++) r[j] += __shfl_down_sync(0xffffffffu, r[j], o);
        }
        if ((t & 31) == 0) {
            #pragma unroll
            for (int j = 0; j < 5; j++) sred5[t >> 5][j] = r[j];
        }
        __syncthreads();
        if (t == 0) {
            float sa = 0.f, sa2 = 0.f, dot1 = 0.f, dot2 = 0.f, vs = 0.f;
            #pragma unroll
            for (int i = 0; i < 8; i++) {
                sa += sred5[i][0]; sa2 += sred5[i][1];
                dot1 += sred5[i][2]; dot2 += sred5[i][3];
                vs += sred5[i][4];
            }
            g_sa[b] = sa;
            g_sa2[b] = sa2;
            g_L[b] = vs * dot1 + vs * dot2;
        }
    }

    // f) pooledInner[b,f] = (1/12) * sum_k S1[k] * qpool[b,k,f] -- 2-way k-split
    if (t < 2 * FD) {
        int f = t % FD, h = t / FD;
        float acc = 0.f;
        const float* qp = g_qpool + (size_t)b * NPOOL + f + h * 64 * FD;
        #pragma unroll 8
        for (int k = 0; k < 64; k++) acc += sS[0][h * 64 + k] * qp[k * FD];
        spf[h][f] = acc;
    }
    __syncthreads();
    if (t < FD) {
        g_pI[b * FD + t] = (spf[0][t] + spf[1][t]) * (1.f / 12.f);
    }
}

// ---------------------------------------------------------------------------
// K3 (fused BN-stats + output). grid FD, block 128.
// ---------------------------------------------------------------------------
__global__ void k_finish(const float* __restrict__ gamma,
                         const float* __restrict__ beta,
                         float* __restrict__ out) {
    int f = blockIdx.x;
    int t = threadIdx.x;

    __shared__ float sPI[BB], sL[BB];
    __shared__ float s_scale, s_shift;

    float m = 0.f, m2 = 0.f;
    if (t < BB) {
        float pi  = g_pI[t * FD + f];
        float L   = g_L[t];
        float sa  = g_sa[t];
        float sa2 = g_sa2[t];
        sPI[t] = pi;
        sL[t]  = L;
        m  = pi * sa + (float)DD * L;
        m2 = pi * pi * sa2 + 2.f * pi * L * sa + (float)DD * L * L;
    }
    if (t < 32) {
        #pragma unroll
        for (int o = 16; o; o >>= 1) {
            m  += __shfl_down_sync(0xffffffffu, m,  o);
            m2 += __shfl_down_sync(0xffffffffu, m2, o);
        }
        if (t == 0) {
            const float inv = 1.f / (float)(BB * DD);
            float mean = m * inv;
            float var  = m2 * inv - mean * mean;
            float scale = gamma[f] * rsqrtf(var + 1e-5f);
            s_scale = scale;
            s_shift = beta[f] - mean * scale;
        }
    }
    __syncthreads();
    float scale = s_scale, shift = s_shift;

    int d = t;
    #pragma unroll 8
    for (int b = 0; b < BB; b++) {
        float val = g_att0[b * DD + d] * sPI[b] + sL[b];
        out[((size_t)b * FD + f) * DD + d] = val * scale + shift;
    }
}

extern "C" void kernel_launch(void* const* d_in, const int* in_sizes, int n_in,
                              void* d_out, int out_size) {
    const float* q     = (const float*)d_in[0];
    const float* v     = (const float*)d_in[1];
    const float* hmat  = (const float*)d_in[2];
    const float* hbias = (const float*)d_in[3];
    const float* gamma = (const float*)d_in[4];
    const float* beta  = (const float*)d_in[5];
    float* out = (float*)d_out;

    k_pass1<<<VBLOCKS + QBLOCKS, 256>>>(v, q);
    k_solve<<<BB, 256>>>(v, hmat, hbias);
    k_finish<<<FD, 128>>>(gamma, beta, out);
}